// round 15
// baseline (speedup 1.0000x reference)
#include <cuda_runtime.h>
#include <cuda_fp16.h>
#include <cstdint>

#define Nn 100000
#define Ee 1000000
#define Rr 3
#define APAD 132
#define PADSZ 64

// ---------------- scratch (device globals, no allocation) ----------------
__device__ float  g_h   [Nn * 64];
__device__ float  g_h0  [Nn * 64];
__device__ float  g_hall[Nn * 64];
__device__ __half g_scal[Nn * 64];     // fp16 messages (dinv*h)
__device__ float  g_acc [Nn * 64];
__device__ float  g_dinv[Rr * Nn];
__device__ int    g_cur [Rr * Nn];
__device__ int    g_pad [(size_t)Rr * Nn * PADSZ];
__device__ float  g_wimg[6 * 8192];
__device__ float  g_bu  [64];

// ---------------- helpers ----------------
__device__ __forceinline__ void fma2(unsigned long long& d, unsigned long long a, unsigned long long b) {
    asm("fma.rn.f32x2 %0,%1,%2,%0;" : "+l"(d) : "l"(a), "l"(b));
}
__device__ __forceinline__ float2 upk2(unsigned long long v) {
    float2 f;
    asm("mov.b64 {%0,%1},%2;" : "=f"(f.x), "=f"(f.y) : "l"(v));
    return f;
}
__device__ __forceinline__ float lrelu(float x) { return x > 0.f ? x : 0.01f * x; }
__device__ __forceinline__ unsigned h2u(float a, float b) {
    __half2 h = __floats2half2_rn(a, b);
    return *(unsigned*)&h;
}

// ---------------- pack (+ cursor zero): weight images + folded U,V,bU ----------------
__global__ void pack_kernel(const float* __restrict__ W1, const float* __restrict__ W2,
                            const float* __restrict__ Wc1, const float* __restrict__ Wc2,
                            const float* __restrict__ W3, const float* __restrict__ b3,
                            const float* __restrict__ bc2) {
    int i = blockIdx.x * 256 + threadIdx.x;
    if (i < Rr * Nn) g_cur[i] = 0;
    if (i < 6 * 4096) {
        int img = i >> 12;
        int e   = i & 4095;
        int k = e >> 6, c = e & 63;
        float v;
        if (img == 0)      v = W1[k * 64 + c];
        else if (img == 1) v = W2[k * 64 + c];
        else if (img == 2) v = Wc1[k * 64 + c];
        else if (img == 3) v = Wc1[(64 + k) * 64 + c];
        else if (img == 4) {                       // U = W3t + Wc2t @ W3b
            float s = W3[k * 64 + c];
            for (int j = 0; j < 64; j++) s += Wc2[k * 64 + j] * W3[(64 + j) * 64 + c];
            v = s;
        } else {                                   // V = Wc2b @ W3b
            float s = 0.f;
            for (int j = 0; j < 64; j++) s += Wc2[(64 + k) * 64 + j] * W3[(64 + j) * 64 + c];
            v = s;
        }
        int g = c >> 3, ii = (c & 7) >> 1, half = c & 1;
        float* o = g_wimg + (size_t)img * 8192 + k * 128 + ii * 32 + g * 4 + half * 2;
        o[0] = v;
        o[1] = v;
    } else if (i < 6 * 4096 + 64) {
        int c = i - 6 * 4096;
        float s = b3[c];
        for (int j = 0; j < 64; j++) s += bc2[j] * W3[(64 + j) * 64 + c];
        g_bu[c] = s;
    }
}

// ---------------- adjacency build ----------------
__global__ void fill_kernel(const int* __restrict__ src, const int* __restrict__ dst) {
    int i = blockIdx.x * 256 + threadIdx.x;
    int r = blockIdx.y;
    if (i >= Ee) return;
    int d = dst[(size_t)r * Ee + i];
    int s = src[(size_t)r * Ee + i];
    int slot = atomicAdd(&g_cur[r * Nn + d], 1);
    if (slot < PADSZ) g_pad[((size_t)r * Nn + d) * PADSZ + slot] = s;
}
__global__ void dinv_kernel() {
    int i = blockIdx.x * 256 + threadIdx.x;
    if (i < Rr * Nn) g_dinv[i] = rsqrtf(fmaxf((float)g_cur[i], 1.0f));
}

// ---------------- pull gather (fp16 source): acc[n] = sum scal[src[e]] ----------------
__global__ __launch_bounds__(256) void gather_kernel(
    const int* __restrict__ pad, const int* __restrict__ cur,
    const __half* __restrict__ scal, float* __restrict__ acc)
{
    int n = blockIdx.x * 8 + (threadIdx.x >> 5);
    if (n >= Nn) return;
    int lane2 = (threadIdx.x & 31) * 2;
    int c = cur[n];
    c = c < PADSZ ? c : PADSZ;
    const int* sp = pad + (size_t)n * PADSZ;
    float2 a0 = {0.f, 0.f}, a1 = {0.f, 0.f}, a2 = {0.f, 0.f}, a3 = {0.f, 0.f};
    int i = 0;
    for (; i + 4 <= c; i += 4) {
        int s0 = sp[i], s1 = sp[i + 1], s2 = sp[i + 2], s3 = sp[i + 3];
        float2 v0 = __half22float2(*(const __half2*)(scal + (size_t)s0 * 64 + lane2));
        float2 v1 = __half22float2(*(const __half2*)(scal + (size_t)s1 * 64 + lane2));
        float2 v2 = __half22float2(*(const __half2*)(scal + (size_t)s2 * 64 + lane2));
        float2 v3 = __half22float2(*(const __half2*)(scal + (size_t)s3 * 64 + lane2));
        a0.x += v0.x; a0.y += v0.y;
        a1.x += v1.x; a1.y += v1.y;
        a2.x += v2.x; a2.y += v2.y;
        a3.x += v3.x; a3.y += v3.y;
    }
    for (; i < c; i++) {
        float2 v0 = __half22float2(*(const __half2*)(scal + (size_t)sp[i] * 64 + lane2));
        a0.x += v0.x; a0.y += v0.y;
    }
    a0.x += a1.x + a2.x + a3.x;
    a0.y += a1.y + a2.y + a3.y;
    *(float2*)(acc + (size_t)n * 64 + lane2) = a0;
}

// ======================================================================
// GEMM core pieces (256 threads, tile 128 nodes x 64 cols,
// thread = 8 nodes x 4 cols, 16 f32x2 accumulators)
//   ng = tid>>4 (node group, n0 = ng*8); cg = tid&15 (col group, c0 = cg*4)
//   W image chunk for cols c0..c0+3: Wd + k*128 + ((cg&1)*2)*32 + (cg>>1)*4, and +32
// ======================================================================
#define GEMM_COMPUTE(As, Wd, n0, wof, acc)                                   \
    _Pragma("unroll 8")                                                      \
    for (int k = 0; k < 64; k++) {                                           \
        int pr = ((k & 7) << 3) | (k >> 3);                                  \
        const float* ar = (As) + pr * APAD + (n0);                           \
        ulonglong2 a01 = *(const ulonglong2*)(ar);                           \
        ulonglong2 a23 = *(const ulonglong2*)(ar + 4);                       \
        const float* wr = (Wd) + k * 128 + (wof);                            \
        ulonglong2 w0 = *(const ulonglong2*)(wr);                            \
        ulonglong2 w1 = *(const ulonglong2*)(wr + 32);                       \
        fma2(acc[0],  a01.x, w0.x); fma2(acc[1],  a01.x, w0.y);              \
        fma2(acc[2],  a01.x, w1.x); fma2(acc[3],  a01.x, w1.y);              \
        fma2(acc[4],  a01.y, w0.x); fma2(acc[5],  a01.y, w0.y);              \
        fma2(acc[6],  a01.y, w1.x); fma2(acc[7],  a01.y, w1.y);              \
        fma2(acc[8],  a23.x, w0.x); fma2(acc[9],  a23.x, w0.y);              \
        fma2(acc[10], a23.x, w1.x); fma2(acc[11], a23.x, w1.y);              \
        fma2(acc[12], a23.y, w0.x); fma2(acc[13], a23.y, w0.y);              \
        fma2(acc[14], a23.y, w1.x); fma2(acc[15], a23.y, w1.y);              \
    }

// ---------------- fused GEMM1+GEMM2: h = act(act(x@W1+b1)@W2+b2); prep scal ----------------
__global__ __launch_bounds__(256, 3) void gemm12_kernel(
    const float* __restrict__ x,
    const float* __restrict__ w1img, const float* __restrict__ b1,
    const float* __restrict__ w2img, const float* __restrict__ b2,
    float* __restrict__ C,
    const float* __restrict__ prep_dinv, __half* __restrict__ scal)
{
    extern __shared__ float sm[];
    float* b1s = sm;
    float* b2s = sm + 64;
    float* As  = sm + 128;
    float* Wd  = sm + 128 + 64 * APAD;

    const int tid  = threadIdx.x;
    const int base = blockIdx.x * 128;
    const int cg   = tid & 15;
    const int n0   = (tid >> 4) << 3;
    const int c0   = cg << 2;
    const int wof  = ((cg & 1) * 2) * 32 + (cg >> 1) * 4;

    if (tid < 16)      ((float4*)b1s)[tid]      = ((const float4*)b1)[tid];
    else if (tid < 32) ((float4*)b2s)[tid - 16] = ((const float4*)b2)[tid - 16];

    unsigned long long acc[16];
#pragma unroll
    for (int i = 0; i < 16; i++) acc[i] = 0ull;

    // ---- phase 1: stage W1 + x ----
    {
        const float4* ws = (const float4*)w1img;
        float4* wdp = (float4*)Wd;
#pragma unroll 4
        for (int j = 0; j < 8; j++) wdp[tid + 256 * j] = ws[tid + 256 * j];
    }
#pragma unroll 4
    for (int it = 0; it < 8; it++) {
        int f  = tid + 256 * it;
        int n  = f >> 4, k4 = f & 15;
        int gnode = base + n;
        float4 v = make_float4(0.f, 0.f, 0.f, 0.f);
        if (gnode < Nn) v = *(const float4*)(x + (size_t)gnode * 64 + k4 * 4);
#pragma unroll
        for (int j = 0; j < 4; j++) {
            int r  = 4 * k4 + j;
            int pr = ((r & 7) << 3) | (r >> 3);
            As[pr * APAD + n] = ((const float*)&v)[j];
        }
    }
    __syncthreads();

    GEMM_COMPUTE(As, Wd, n0, wof, acc)
    __syncthreads();

    // ---- write h0 tile (activated) back into As; restage W2 ----
    {
        const float4 bb = *(const float4*)(b1s + c0);
#pragma unroll
        for (int np = 0; np < 4; np++) {
            float2 p0 = upk2(acc[np * 4 + 0]);
            float2 p1 = upk2(acc[np * 4 + 1]);
            float2 p2 = upk2(acc[np * 4 + 2]);
            float2 p3 = upk2(acc[np * 4 + 3]);
#pragma unroll
            for (int half = 0; half < 2; half++) {
                int n = n0 + 2 * np + half;
                float z[4];
                z[0] = lrelu((half ? p0.y : p0.x) + bb.x);
                z[1] = lrelu((half ? p1.y : p1.x) + bb.y);
                z[2] = lrelu((half ? p2.y : p2.x) + bb.z);
                z[3] = lrelu((half ? p3.y : p3.x) + bb.w);
#pragma unroll
                for (int j = 0; j < 4; j++) {
                    int k  = c0 + j;
                    int pr = ((k & 7) << 3) | (k >> 3);
                    As[pr * APAD + n] = z[j];
                }
            }
        }
        const float4* ws = (const float4*)w2img;
        float4* wdp = (float4*)Wd;
#pragma unroll 4
        for (int j = 0; j < 8; j++) wdp[tid + 256 * j] = ws[tid + 256 * j];
    }
#pragma unroll
    for (int i = 0; i < 16; i++) acc[i] = 0ull;
    __syncthreads();

    GEMM_COMPUTE(As, Wd, n0, wof, acc)

    // ---- epilogue: h = act(.+b2); scal = fp16(dinv*h) ----
    const float4 bi = *(const float4*)(b2s + c0);
#pragma unroll
    for (int np = 0; np < 4; np++) {
        float2 p0 = upk2(acc[np * 4 + 0]);
        float2 p1 = upk2(acc[np * 4 + 1]);
        float2 p2 = upk2(acc[np * 4 + 2]);
        float2 p3 = upk2(acc[np * 4 + 3]);
#pragma unroll
        for (int half = 0; half < 2; half++) {
            int gnode = base + n0 + 2 * np + half;
            if (gnode >= Nn) continue;
            float4 v;
            v.x = lrelu((half ? p0.y : p0.x) + bi.x);
            v.y = lrelu((half ? p1.y : p1.x) + bi.y);
            v.z = lrelu((half ? p2.y : p2.x) + bi.z);
            v.w = lrelu((half ? p3.y : p3.x) + bi.w);
            size_t idx = (size_t)gnode * 64 + c0;
            *(float4*)(C + idx) = v;
            float dv = prep_dinv[gnode];
            uint2 hv;
            hv.x = h2u(v.x * dv, v.y * dv);
            hv.y = h2u(v.z * dv, v.w * dv);
            *(uint2*)(scal + idx) = hv;
        }
    }
}

// ---------------- v5 FFMA2 fused dual GEMM (+ optional fused final head) ----------------
// hall_mode: 0 none, 1 set, 2 add, 3 add-in-reg + out = lrelu(hall+v)@W4+b4
__global__ __launch_bounds__(256, 3) void gemm_v5_kernel(
    const float* __restrict__ A, const float* __restrict__ B,
    const float* __restrict__ rowscaleB,
    const float* __restrict__ wimg, int nchunks,
    const float* __restrict__ bias, float* __restrict__ C,
    float* __restrict__ hall, int hall_mode, int act,
    const float* __restrict__ prep_dinv, __half* __restrict__ scal,
    const float* __restrict__ W4, const float* __restrict__ b4,
    float* __restrict__ out)
{
    extern __shared__ float sm[];
    float* bias_s = sm;
    float* As     = sm + 64;
    float* Wd     = sm + 64 + 64 * APAD;

    const int tid  = threadIdx.x;
    const int base = blockIdx.x * 128;
    const int cg   = tid & 15;
    const int n0   = (tid >> 4) << 3;
    const int c0   = cg << 2;
    const int wof  = ((cg & 1) * 2) * 32 + (cg >> 1) * 4;

    if (tid < 16) ((float4*)bias_s)[tid] = ((const float4*)bias)[tid];

    unsigned long long acc[16];
#pragma unroll
    for (int i = 0; i < 16; i++) acc[i] = 0ull;

    for (int ch = 0; ch < nchunks; ch++) {
        {
            const float4* ws = (const float4*)(wimg + (size_t)ch * 8192);
            float4* wdp = (float4*)Wd;
#pragma unroll 4
            for (int j = 0; j < 8; j++) wdp[tid + 256 * j] = ws[tid + 256 * j];
        }
        {
            const float* Am = ch ? B : A;
#pragma unroll 4
            for (int it = 0; it < 8; it++) {
                int f  = tid + 256 * it;
                int n  = f >> 4, k4 = f & 15;
                int gnode = base + n;
                float4 v = make_float4(0.f, 0.f, 0.f, 0.f);
                float s = 1.0f;
                if (gnode < Nn) {
                    v = *(const float4*)(Am + (size_t)gnode * 64 + k4 * 4);
                    if (ch == 1 && rowscaleB) s = -rowscaleB[gnode];
                }
                float vv[4] = {v.x * s, v.y * s, v.z * s, v.w * s};
#pragma unroll
                for (int j = 0; j < 4; j++) {
                    int r  = 4 * k4 + j;
                    int pr = ((r & 7) << 3) | (r >> 3);
                    As[pr * APAD + n] = vv[j];
                }
            }
        }
        __syncthreads();

        GEMM_COMPUTE(As, Wd, n0, wof, acc)
        __syncthreads();
    }

    const float4 bi = *(const float4*)(bias_s + c0);

    if (hall_mode == 3) {
        // ---- fused final head: out = lrelu(hall + v) @ W4 + b4 ----
        float w4a[4], w4b[4];
#pragma unroll
        for (int j = 0; j < 4; j++) {
            float2 w = *(const float2*)(W4 + (c0 + j) * 2);
            w4a[j] = w.x; w4b[j] = w.y;
        }
        float o0[8], o1[8];
#pragma unroll
        for (int j = 0; j < 8; j++) { o0[j] = 0.f; o1[j] = 0.f; }
#pragma unroll
        for (int np = 0; np < 4; np++) {
            float2 p0 = upk2(acc[np * 4 + 0]);
            float2 p1 = upk2(acc[np * 4 + 1]);
            float2 p2 = upk2(acc[np * 4 + 2]);
            float2 p3 = upk2(acc[np * 4 + 3]);
#pragma unroll
            for (int half = 0; half < 2; half++) {
                int ni = 2 * np + half;
                int gnode = base + n0 + ni;
                if (gnode >= Nn) continue;
                size_t idx = (size_t)gnode * 64 + c0;
                float4 hv = *(const float4*)(hall + idx);
                float z0 = lrelu(hv.x + (half ? p0.y : p0.x) + bi.x);
                float z1 = lrelu(hv.y + (half ? p1.y : p1.x) + bi.y);
                float z2 = lrelu(hv.z + (half ? p2.y : p2.x) + bi.z);
                float z3 = lrelu(hv.w + (half ? p3.y : p3.x) + bi.w);
                o0[ni] = z0 * w4a[0] + z1 * w4a[1] + z2 * w4a[2] + z3 * w4a[3];
                o1[ni] = z0 * w4b[0] + z1 * w4b[1] + z2 * w4b[2] + z3 * w4b[3];
            }
        }
        // reduce across the 16 column-group lanes (same n0: lane bit4 preserved)
#pragma unroll
        for (int ni = 0; ni < 8; ni++) {
#pragma unroll
            for (int m = 1; m < 16; m <<= 1) {
                o0[ni] += __shfl_xor_sync(0xFFFFFFFFu, o0[ni], m);
                o1[ni] += __shfl_xor_sync(0xFFFFFFFFu, o1[ni], m);
            }
        }
        if (cg == 0) {
            float2 bb = *(const float2*)b4;
#pragma unroll
            for (int ni = 0; ni < 8; ni++) {
                int gnode = base + n0 + ni;
                if (gnode < Nn)
                    *(float2*)(out + (size_t)gnode * 2) = make_float2(o0[ni] + bb.x, o1[ni] + bb.y);
            }
        }
        return;
    }

    // ---- standard fused epilogue ----
#pragma unroll
    for (int np = 0; np < 4; np++) {
        float2 p0 = upk2(acc[np * 4 + 0]);
        float2 p1 = upk2(acc[np * 4 + 1]);
        float2 p2 = upk2(acc[np * 4 + 2]);
        float2 p3 = upk2(acc[np * 4 + 3]);
#pragma unroll
        for (int half = 0; half < 2; half++) {
            int gnode = base + n0 + 2 * np + half;
            if (gnode >= Nn) continue;
            float4 v;
            v.x = (half ? p0.y : p0.x) + bi.x;
            v.y = (half ? p1.y : p1.x) + bi.y;
            v.z = (half ? p2.y : p2.x) + bi.z;
            v.w = (half ? p3.y : p3.x) + bi.w;
            if (act) {
                v.x = lrelu(v.x); v.y = lrelu(v.y); v.z = lrelu(v.z); v.w = lrelu(v.w);
            }
            size_t idx = (size_t)gnode * 64 + c0;
            *(float4*)(C + idx) = v;
            if (hall_mode == 1) {
                *(float4*)(hall + idx) = v;
            } else if (hall_mode == 2) {
                float4 hv = *(const float4*)(hall + idx);
                hv.x += v.x; hv.y += v.y; hv.z += v.z; hv.w += v.w;
                *(float4*)(hall + idx) = hv;
            }
            if (scal) {
                float dv = prep_dinv[gnode];
                uint2 hv;
                hv.x = h2u(v.x * dv, v.y * dv);
                hv.y = h2u(v.z * dv, v.w * dv);
                *(uint2*)(scal + idx) = hv;
            }
        }
    }
}

// ---------------- launch ----------------
#define GSMEM   ((64 + 64 * APAD + 64 * 128) * 4)    // 66816 bytes
#define GSMEM12 ((128 + 64 * APAD + 64 * 128) * 4)   // 67072 bytes

extern "C" void kernel_launch(void* const* d_in, const int* in_sizes, int n_in,
                              void* d_out, int out_size)
{
    const float* x   = (const float*)d_in[0];
    const int*   src = (const int*)d_in[1];
    const int*   dst = (const int*)d_in[2];
    const float* W1  = (const float*)d_in[3];
    const float* b1  = (const float*)d_in[4];
    const float* W2  = (const float*)d_in[5];
    const float* b2  = (const float*)d_in[6];
    const float* Wc1 = (const float*)d_in[7];
    const float* bc1 = (const float*)d_in[8];
    const float* Wc2 = (const float*)d_in[9];
    const float* bc2 = (const float*)d_in[10];
    const float* W3  = (const float*)d_in[11];
    const float* b3  = (const float*)d_in[12];
    const float* W4  = (const float*)d_in[13];
    const float* b4  = (const float*)d_in[14];
    float* out = (float*)d_out;

    cudaFuncSetAttribute(gemm_v5_kernel, cudaFuncAttributeMaxDynamicSharedMemorySize, GSMEM);
    cudaFuncSetAttribute(gemm12_kernel,  cudaFuncAttributeMaxDynamicSharedMemorySize, GSMEM12);

    void *p;
    float *h, *h0, *hall, *acc, *dinv, *wimg, *bu;
    __half* scal;
    int *cur, *pad;
    cudaGetSymbolAddress(&p, g_h);    h    = (float*)p;
    cudaGetSymbolAddress(&p, g_h0);   h0   = (float*)p;
    cudaGetSymbolAddress(&p, g_hall); hall = (float*)p;
    cudaGetSymbolAddress(&p, g_scal); scal = (__half*)p;
    cudaGetSymbolAddress(&p, g_acc);  acc  = (float*)p;
    cudaGetSymbolAddress(&p, g_dinv); dinv = (float*)p;
    cudaGetSymbolAddress(&p, g_wimg); wimg = (float*)p;
    cudaGetSymbolAddress(&p, g_bu);   bu   = (float*)p;
    cudaGetSymbolAddress(&p, g_cur);  cur  = (int*)p;
    cudaGetSymbolAddress(&p, g_pad);  pad  = (int*)p;

    const int GB = (Nn + 127) / 128;      // 782 gemm blocks
    const int AB = (Nn + 7) / 8;          // 12500 gather blocks

    pack_kernel<<<(Rr * Nn + 255) / 256, 256>>>(W1, W2, Wc1, Wc2, W3, b3, bc2);
    {
        dim3 fg((Ee + 255) / 256, Rr);
        fill_kernel<<<fg, 256>>>(src, dst);
    }
    dinv_kernel<<<(Rr * Nn + 255) / 256, 256>>>();

    // fused: h = act(act(x@W1+b1)@W2+b2); scal = fp16(dinv_r0 * h)
    gemm12_kernel<<<GB, 256, GSMEM12>>>(x, wimg + 0 * 8192, b1, wimg + 1 * 8192, b2,
                                        h, dinv, scal);

    for (int r = 0; r < Rr; r++) {
        const float* dv = dinv + (size_t)r * Nn;
        const int*   pr = pad + (size_t)r * Nn * PADSZ;
        const int*   cr = cur + (size_t)r * Nn;

        gather_kernel<<<AB, 256>>>(pr, cr, scal, acc);
        gemm_v5_kernel<<<GB, 256, GSMEM>>>(h, acc, dv, wimg + 2 * 8192, 2,
                                           bc1, h0, nullptr, 0, 0, dv, scal,
                                           nullptr, nullptr, nullptr);

        gather_kernel<<<AB, 256>>>(pr, cr, scal, acc);
        if (r + 1 < Rr) {
            const float* ndv = dinv + (size_t)(r + 1) * Nn;
            gemm_v5_kernel<<<GB, 256, GSMEM>>>(h0, acc, dv, wimg + 4 * 8192, 2,
                                               bu, h, hall, (r == 0) ? 1 : 2, 0,
                                               ndv, scal, nullptr, nullptr, nullptr);
        } else {
            gemm_v5_kernel<<<GB, 256, GSMEM>>>(h0, acc, dv, wimg + 4 * 8192, 2,
                                               bu, h, hall, 3, 0,
                                               nullptr, nullptr, W4, b4, out);
        }
    }
}

// round 16
// speedup vs baseline: 1.4295x; 1.4295x over previous
#include <cuda_runtime.h>
#include <cuda_fp16.h>
#include <cstdint>

#define Nn 100000
#define Ee 1000000
#define Rr 3
#define APAD 132
#define PADSZ 64
#define WROW 72
#define WIMG (64 * WROW)   // 4608 floats per image

// ---------------- scratch (device globals, no allocation) ----------------
__device__ float  g_h   [Nn * 64];
__device__ float  g_h0  [Nn * 64];
__device__ float  g_hall[Nn * 64];
__device__ __half g_scal[Nn * 64];     // fp16 messages (dinv*h)
__device__ float  g_acc [Nn * 64];
__device__ float  g_dinv[Rr * Nn];
__device__ int    g_cur [Rr * Nn];
__device__ int    g_pad [(size_t)Rr * Nn * PADSZ];
__device__ float  g_wimg[6 * WIMG];
__device__ float  g_bu  [64];

// ---------------- helpers ----------------
__device__ __forceinline__ void fma2(unsigned long long& d, unsigned long long a, unsigned long long b) {
    asm("fma.rn.f32x2 %0,%1,%2,%0;" : "+l"(d) : "l"(a), "l"(b));
}
__device__ __forceinline__ unsigned long long pk2s(float a) {
    unsigned long long r;
    asm("mov.b64 %0,{%1,%1};" : "=l"(r) : "f"(a));
    return r;
}
__device__ __forceinline__ float2 upk2(unsigned long long v) {
    float2 f;
    asm("mov.b64 {%0,%1},%2;" : "=f"(f.x), "=f"(f.y) : "l"(v));
    return f;
}
__device__ __forceinline__ float lrelu(float x) { return x > 0.f ? x : 0.01f * x; }
__device__ __forceinline__ unsigned h2u(float a, float b) {
    __half2 h = __floats2half2_rn(a, b);
    return *(unsigned*)&h;
}

// ---------------- pack (+ cursor zero): natural-pair weight images + folded U,V,bU ----------------
// image row k (WROW floats): [half 0: cols 8g..8g+3 by g 0..7][half 1: cols 8g+4..8g+7 by g]
__global__ void pack_kernel(const float* __restrict__ W1, const float* __restrict__ W2,
                            const float* __restrict__ Wc1, const float* __restrict__ Wc2,
                            const float* __restrict__ W3, const float* __restrict__ b3,
                            const float* __restrict__ bc2) {
    int i = blockIdx.x * 256 + threadIdx.x;
    if (i < Rr * Nn) g_cur[i] = 0;
    if (i < 6 * 4096) {
        int img = i >> 12;
        int e   = i & 4095;
        int k = e >> 6, c = e & 63;
        float v;
        if (img == 0)      v = W1[k * 64 + c];
        else if (img == 1) v = W2[k * 64 + c];
        else if (img == 2) v = Wc1[k * 64 + c];
        else if (img == 3) v = Wc1[(64 + k) * 64 + c];
        else if (img == 4) {                       // U = W3t + Wc2t @ W3b
            float s = W3[k * 64 + c];
            for (int j = 0; j < 64; j++) s += Wc2[k * 64 + j] * W3[(64 + j) * 64 + c];
            v = s;
        } else {                                   // V = Wc2b @ W3b
            float s = 0.f;
            for (int j = 0; j < 64; j++) s += Wc2[(64 + k) * 64 + j] * W3[(64 + j) * 64 + c];
            v = s;
        }
        int g = c >> 3, j = c & 7;
        int pos = (j >> 2) * 32 + g * 4 + (j & 3);
        g_wimg[(size_t)img * WIMG + k * WROW + pos] = v;
    } else if (i < 6 * 4096 + 64) {
        int c = i - 6 * 4096;
        float s = b3[c];
        for (int j = 0; j < 64; j++) s += bc2[j] * W3[(64 + j) * 64 + c];
        g_bu[c] = s;
    }
}

// ---------------- adjacency build ----------------
__global__ void fill_kernel(const int* __restrict__ src, const int* __restrict__ dst) {
    int i = blockIdx.x * 256 + threadIdx.x;
    int r = blockIdx.y;
    if (i >= Ee) return;
    int d = dst[(size_t)r * Ee + i];
    int s = src[(size_t)r * Ee + i];
    int slot = atomicAdd(&g_cur[r * Nn + d], 1);
    if (slot < PADSZ) g_pad[((size_t)r * Nn + d) * PADSZ + slot] = s;
}
__global__ void dinv_kernel() {
    int i = blockIdx.x * 256 + threadIdx.x;
    if (i < Rr * Nn) g_dinv[i] = rsqrtf(fmaxf((float)g_cur[i], 1.0f));
}

// ---------------- pull gather (fp16 source): acc[n] = sum scal[src[e]] ----------------
__global__ __launch_bounds__(256) void gather_kernel(
    const int* __restrict__ pad, const int* __restrict__ cur,
    const __half* __restrict__ scal, float* __restrict__ acc)
{
    int n = blockIdx.x * 8 + (threadIdx.x >> 5);
    if (n >= Nn) return;
    int lane2 = (threadIdx.x & 31) * 2;
    int c = cur[n];
    c = c < PADSZ ? c : PADSZ;
    const int* sp = pad + (size_t)n * PADSZ;
    float2 a0 = {0.f, 0.f}, a1 = {0.f, 0.f}, a2 = {0.f, 0.f}, a3 = {0.f, 0.f};
    int i = 0;
    for (; i + 4 <= c; i += 4) {
        int s0 = sp[i], s1 = sp[i + 1], s2 = sp[i + 2], s3 = sp[i + 3];
        float2 v0 = __half22float2(*(const __half2*)(scal + (size_t)s0 * 64 + lane2));
        float2 v1 = __half22float2(*(const __half2*)(scal + (size_t)s1 * 64 + lane2));
        float2 v2 = __half22float2(*(const __half2*)(scal + (size_t)s2 * 64 + lane2));
        float2 v3 = __half22float2(*(const __half2*)(scal + (size_t)s3 * 64 + lane2));
        a0.x += v0.x; a0.y += v0.y;
        a1.x += v1.x; a1.y += v1.y;
        a2.x += v2.x; a2.y += v2.y;
        a3.x += v3.x; a3.y += v3.y;
    }
    for (; i < c; i++) {
        float2 v0 = __half22float2(*(const __half2*)(scal + (size_t)sp[i] * 64 + lane2));
        a0.x += v0.x; a0.y += v0.y;
    }
    a0.x += a1.x + a2.x + a3.x;
    a0.y += a1.y + a2.y + a3.y;
    *(float2*)(acc + (size_t)n * 64 + lane2) = a0;
}

// ======================================================================
// GEMM core (128 threads, tile 128 nodes x 64 cols, thread = 8 nodes x 8 cols)
//   g = tid&7 (col group: cols 8g..8g+7), n0 = (tid>>3)*8
//   acc[ni*4 + cp] = f32x2 over cols (c0+2cp, c0+2cp+1) for node n0+ni
//   per k: 2 A LDS.128 (1 wf each) + 2 W LDS.128 (1 wf each) + 8 dup-movs + 32 FMA2
// ======================================================================
#define GEMM_COMPUTE(As, Wd, n0, g, acc)                                       \
    _Pragma("unroll 8")                                                        \
    for (int k = 0; k < 64; k++) {                                             \
        int pr = ((k & 7) << 3) | (k >> 3);                                    \
        const float* ar = (As) + pr * APAD + (n0);                             \
        float4 af0 = *(const float4*)(ar);                                     \
        float4 af1 = *(const float4*)(ar + 4);                                 \
        const float* wr = (Wd) + k * WROW + (g) * 4;                           \
        ulonglong2 wA = *(const ulonglong2*)(wr);        /* (c0,c0+1),(c0+2,c0+3) */ \
        ulonglong2 wB = *(const ulonglong2*)(wr + 32);   /* (c0+4..7) */       \
        unsigned long long an0 = pk2s(af0.x), an1 = pk2s(af0.y);               \
        unsigned long long an2 = pk2s(af0.z), an3 = pk2s(af0.w);               \
        unsigned long long an4 = pk2s(af1.x), an5 = pk2s(af1.y);               \
        unsigned long long an6 = pk2s(af1.z), an7 = pk2s(af1.w);               \
        fma2(acc[0],  an0, wA.x); fma2(acc[1],  an0, wA.y);                    \
        fma2(acc[2],  an0, wB.x); fma2(acc[3],  an0, wB.y);                    \
        fma2(acc[4],  an1, wA.x); fma2(acc[5],  an1, wA.y);                    \
        fma2(acc[6],  an1, wB.x); fma2(acc[7],  an1, wB.y);                    \
        fma2(acc[8],  an2, wA.x); fma2(acc[9],  an2, wA.y);                    \
        fma2(acc[10], an2, wB.x); fma2(acc[11], an2, wB.y);                    \
        fma2(acc[12], an3, wA.x); fma2(acc[13], an3, wA.y);                    \
        fma2(acc[14], an3, wB.x); fma2(acc[15], an3, wB.y);                    \
        fma2(acc[16], an4, wA.x); fma2(acc[17], an4, wA.y);                    \
        fma2(acc[18], an4, wB.x); fma2(acc[19], an4, wB.y);                    \
        fma2(acc[20], an5, wA.x); fma2(acc[21], an5, wA.y);                    \
        fma2(acc[22], an5, wB.x); fma2(acc[23], an5, wB.y);                    \
        fma2(acc[24], an6, wA.x); fma2(acc[25], an6, wA.y);                    \
        fma2(acc[26], an6, wB.x); fma2(acc[27], an6, wB.y);                    \
        fma2(acc[28], an7, wA.x); fma2(acc[29], an7, wA.y);                    \
        fma2(acc[30], an7, wB.x); fma2(acc[31], an7, wB.y);                    \
    }

// unpack node ni's 8 cols (+bias) from acc
#define NODE_V(acc, ni, bi0, bi1, v0, v1)                                      \
    {                                                                          \
        float2 q0 = upk2(acc[(ni) * 4 + 0]);                                   \
        float2 q1 = upk2(acc[(ni) * 4 + 1]);                                   \
        float2 q2 = upk2(acc[(ni) * 4 + 2]);                                   \
        float2 q3 = upk2(acc[(ni) * 4 + 3]);                                   \
        v0 = make_float4(q0.x + bi0.x, q0.y + bi0.y, q1.x + bi0.z, q1.y + bi0.w); \
        v1 = make_float4(q2.x + bi1.x, q2.y + bi1.y, q3.x + bi1.z, q3.y + bi1.w); \
    }

// ---------------- fused GEMM1+GEMM2: h = act(act(x@W1+b1)@W2+b2); prep scal ----------------
__global__ __launch_bounds__(128, 3) void gemm12_kernel(
    const float* __restrict__ x,
    const float* __restrict__ w1img, const float* __restrict__ b1,
    const float* __restrict__ w2img, const float* __restrict__ b2,
    float* __restrict__ C,
    const float* __restrict__ prep_dinv, __half* __restrict__ scal)
{
    extern __shared__ float sm[];
    float* b1s = sm;
    float* b2s = sm + 64;
    float* As  = sm + 128;
    float* Wd  = sm + 128 + 64 * APAD;

    const int tid  = threadIdx.x;
    const int base = blockIdx.x * 128;
    const int g    = tid & 7;
    const int n0   = (tid >> 3) << 3;
    const int c0   = g << 3;

    if (tid < 16)      ((float4*)b1s)[tid]      = ((const float4*)b1)[tid];
    else if (tid < 32) ((float4*)b2s)[tid - 16] = ((const float4*)b2)[tid - 16];

    unsigned long long acc[32];
#pragma unroll
    for (int i = 0; i < 32; i++) acc[i] = 0ull;

    // ---- phase 1: stage W1 (1152 float4 = 9x128) + x ----
    {
        const float4* ws = (const float4*)w1img;
        float4* wdp = (float4*)Wd;
#pragma unroll 3
        for (int j = 0; j < 9; j++) wdp[tid + 128 * j] = ws[tid + 128 * j];
    }
#pragma unroll 4
    for (int it = 0; it < 16; it++) {
        int f  = tid + 128 * it;
        int n  = f >> 4, k4 = f & 15;
        int gnode = base + n;
        float4 v = make_float4(0.f, 0.f, 0.f, 0.f);
        if (gnode < Nn) v = *(const float4*)(x + (size_t)gnode * 64 + k4 * 4);
#pragma unroll
        for (int j = 0; j < 4; j++) {
            int r  = 4 * k4 + j;
            int pr = ((r & 7) << 3) | (r >> 3);
            As[pr * APAD + n] = ((const float*)&v)[j];
        }
    }
    __syncthreads();

    GEMM_COMPUTE(As, Wd, n0, g, acc)
    __syncthreads();

    // ---- write h0 tile (activated) back into As; restage W2 ----
    {
        const float4 bb0 = *(const float4*)(b1s + c0);
        const float4 bb1 = *(const float4*)(b1s + c0 + 4);
#pragma unroll
        for (int ni = 0; ni < 8; ni++) {
            int n = n0 + ni;
            float4 v0, v1;
            NODE_V(acc, ni, bb0, bb1, v0, v1)
            float z[8];
            z[0] = lrelu(v0.x); z[1] = lrelu(v0.y); z[2] = lrelu(v0.z); z[3] = lrelu(v0.w);
            z[4] = lrelu(v1.x); z[5] = lrelu(v1.y); z[6] = lrelu(v1.z); z[7] = lrelu(v1.w);
#pragma unroll
            for (int j = 0; j < 8; j++) {
                int k  = c0 + j;
                int pr = ((k & 7) << 3) | (k >> 3);
                As[pr * APAD + n] = z[j];
            }
        }
        const float4* ws = (const float4*)w2img;
        float4* wdp = (float4*)Wd;
#pragma unroll 3
        for (int j = 0; j < 9; j++) wdp[tid + 128 * j] = ws[tid + 128 * j];
    }
#pragma unroll
    for (int i = 0; i < 32; i++) acc[i] = 0ull;
    __syncthreads();

    GEMM_COMPUTE(As, Wd, n0, g, acc)

    // ---- epilogue: h = act(.+b2); scal = fp16(dinv*h) ----
    const float4 bi0 = *(const float4*)(b2s + c0);
    const float4 bi1 = *(const float4*)(b2s + c0 + 4);
#pragma unroll
    for (int ni = 0; ni < 8; ni++) {
        int gnode = base + n0 + ni;
        if (gnode >= Nn) continue;
        float4 v0, v1;
        NODE_V(acc, ni, bi0, bi1, v0, v1)
        v0.x = lrelu(v0.x); v0.y = lrelu(v0.y); v0.z = lrelu(v0.z); v0.w = lrelu(v0.w);
        v1.x = lrelu(v1.x); v1.y = lrelu(v1.y); v1.z = lrelu(v1.z); v1.w = lrelu(v1.w);
        size_t idx = (size_t)gnode * 64 + c0;
        *(float4*)(C + idx)     = v0;
        *(float4*)(C + idx + 4) = v1;
        float dv = prep_dinv[gnode];
        uint4 hv;
        hv.x = h2u(v0.x * dv, v0.y * dv);
        hv.y = h2u(v0.z * dv, v0.w * dv);
        hv.z = h2u(v1.x * dv, v1.y * dv);
        hv.w = h2u(v1.z * dv, v1.w * dv);
        *(uint4*)(scal + idx) = hv;
    }
}

// ---------------- v6 FFMA2 fused dual GEMM (+ optional fused final head) ----------------
// hall_mode: 0 none, 1 set, 2 add, 3 add-in-reg + out = lrelu(hall+v)@W4+b4
__global__ __launch_bounds__(128, 3) void gemm_v6_kernel(
    const float* __restrict__ A, const float* __restrict__ B,
    const float* __restrict__ rowscaleB,
    const float* __restrict__ wimg, int nchunks,
    const float* __restrict__ bias, float* __restrict__ C,
    float* __restrict__ hall, int hall_mode, int act,
    const float* __restrict__ prep_dinv, __half* __restrict__ scal,
    const float* __restrict__ W4, const float* __restrict__ b4,
    float* __restrict__ out)
{
    extern __shared__ float sm[];
    float* bias_s = sm;
    float* As     = sm + 64;
    float* Wd     = sm + 64 + 64 * APAD;

    const int tid  = threadIdx.x;
    const int base = blockIdx.x * 128;
    const int g    = tid & 7;
    const int n0   = (tid >> 3) << 3;
    const int c0   = g << 3;

    if (tid < 16) ((float4*)bias_s)[tid] = ((const float4*)bias)[tid];

    unsigned long long acc[32];
#pragma unroll
    for (int i = 0; i < 32; i++) acc[i] = 0ull;

    for (int ch = 0; ch < nchunks; ch++) {
        {
            const float4* ws = (const float4*)(wimg + (size_t)ch * WIMG);
            float4* wdp = (float4*)Wd;
#pragma unroll 3
            for (int j = 0; j < 9; j++) wdp[tid + 128 * j] = ws[tid + 128 * j];
        }
        {
            const float* Am = ch ? B : A;
#pragma unroll 4
            for (int it = 0; it < 16; it++) {
                int f  = tid + 128 * it;
                int n  = f >> 4, k4 = f & 15;
                int gnode = base + n;
                float4 v = make_float4(0.f, 0.f, 0.f, 0.f);
                float s = 1.0f;
                if (gnode < Nn) {
                    v = *(const float4*)(Am + (size_t)gnode * 64 + k4 * 4);
                    if (ch == 1 && rowscaleB) s = -rowscaleB[gnode];
                }
                float vv[4] = {v.x * s, v.y * s, v.z * s, v.w * s};
#pragma unroll
                for (int j = 0; j < 4; j++) {
                    int r  = 4 * k4 + j;
                    int pr = ((r & 7) << 3) | (r >> 3);
                    As[pr * APAD + n] = vv[j];
                }
            }
        }
        __syncthreads();

        GEMM_COMPUTE(As, Wd, n0, g, acc)
        __syncthreads();
    }

    const float4 bi0 = *(const float4*)(bias_s + c0);
    const float4 bi1 = *(const float4*)(bias_s + c0 + 4);

    if (hall_mode == 3) {
        // ---- fused final head: out = lrelu(hall + v) @ W4 + b4 ----
        float w4a[8], w4b[8];
#pragma unroll
        for (int j = 0; j < 8; j++) {
            float2 w = *(const float2*)(W4 + (c0 + j) * 2);
            w4a[j] = w.x; w4b[j] = w.y;
        }
        float o0[8], o1[8];
#pragma unroll
        for (int j = 0; j < 8; j++) { o0[j] = 0.f; o1[j] = 0.f; }
#pragma unroll
        for (int ni = 0; ni < 8; ni++) {
            int gnode = base + n0 + ni;
            if (gnode >= Nn) continue;
            size_t idx = (size_t)gnode * 64 + c0;
            float4 h0v = *(const float4*)(hall + idx);
            float4 h1v = *(const float4*)(hall + idx + 4);
            float4 v0, v1;
            NODE_V(acc, ni, bi0, bi1, v0, v1)
            float z0 = lrelu(h0v.x + v0.x);
            float z1 = lrelu(h0v.y + v0.y);
            float z2 = lrelu(h0v.z + v0.z);
            float z3 = lrelu(h0v.w + v0.w);
            float z4 = lrelu(h1v.x + v1.x);
            float z5 = lrelu(h1v.y + v1.y);
            float z6 = lrelu(h1v.z + v1.z);
            float z7 = lrelu(h1v.w + v1.w);
            o0[ni] = z0 * w4a[0] + z1 * w4a[1] + z2 * w4a[2] + z3 * w4a[3]
                   + z4 * w4a[4] + z5 * w4a[5] + z6 * w4a[6] + z7 * w4a[7];
            o1[ni] = z0 * w4b[0] + z1 * w4b[1] + z2 * w4b[2] + z3 * w4b[3]
                   + z4 * w4b[4] + z5 * w4b[5] + z6 * w4b[6] + z7 * w4b[7];
        }
#pragma unroll
        for (int ni = 0; ni < 8; ni++) {
#pragma unroll
            for (int m = 1; m < 8; m <<= 1) {
                o0[ni] += __shfl_xor_sync(0xFFFFFFFFu, o0[ni], m);
                o1[ni] += __shfl_xor_sync(0xFFFFFFFFu, o1[ni], m);
            }
        }
        if (g == 0) {
            float2 bb = *(const float2*)b4;
#pragma unroll
            for (int ni = 0; ni < 8; ni++) {
                int gnode = base + n0 + ni;
                if (gnode < Nn)
                    *(float2*)(out + (size_t)gnode * 2) = make_float2(o0[ni] + bb.x, o1[ni] + bb.y);
            }
        }
        return;
    }

    // ---- standard fused epilogue ----
#pragma unroll
    for (int ni = 0; ni < 8; ni++) {
        int gnode = base + n0 + ni;
        if (gnode >= Nn) continue;
        float4 v0, v1;
        NODE_V(acc, ni, bi0, bi1, v0, v1)
        if (act) {
            v0.x = lrelu(v0.x); v0.y = lrelu(v0.y); v0.z = lrelu(v0.z); v0.w = lrelu(v0.w);
            v1.x = lrelu(v1.x); v1.y = lrelu(v1.y); v1.z = lrelu(v1.z); v1.w = lrelu(v1.w);
        }
        size_t idx = (size_t)gnode * 64 + c0;
        *(float4*)(C + idx)     = v0;
        *(float4*)(C + idx + 4) = v1;
        if (hall_mode == 1) {
            *(float4*)(hall + idx)     = v0;
            *(float4*)(hall + idx + 4) = v1;
        } else if (hall_mode == 2) {
            float4 h0v = *(const float4*)(hall + idx);
            float4 h1v = *(const float4*)(hall + idx + 4);
            h0v.x += v0.x; h0v.y += v0.y; h0v.z += v0.z; h0v.w += v0.w;
            h1v.x += v1.x; h1v.y += v1.y; h1v.z += v1.z; h1v.w += v1.w;
            *(float4*)(hall + idx)     = h0v;
            *(float4*)(hall + idx + 4) = h1v;
        }
        if (scal) {
            float dv = prep_dinv[gnode];
            uint4 hv;
            hv.x = h2u(v0.x * dv, v0.y * dv);
            hv.y = h2u(v0.z * dv, v0.w * dv);
            hv.z = h2u(v1.x * dv, v1.y * dv);
            hv.w = h2u(v1.z * dv, v1.w * dv);
            *(uint4*)(scal + idx) = hv;
        }
    }
}

// ---------------- launch ----------------
#define GSMEM   ((64 + 64 * APAD + 64 * WROW) * 4)    // 52480 bytes
#define GSMEM12 ((128 + 64 * APAD + 64 * WROW) * 4)   // 52736 bytes

extern "C" void kernel_launch(void* const* d_in, const int* in_sizes, int n_in,
                              void* d_out, int out_size)
{
    const float* x   = (const float*)d_in[0];
    const int*   src = (const int*)d_in[1];
    const int*   dst = (const int*)d_in[2];
    const float* W1  = (const float*)d_in[3];
    const float* b1  = (const float*)d_in[4];
    const float* W2  = (const float*)d_in[5];
    const float* b2  = (const float*)d_in[6];
    const float* Wc1 = (const float*)d_in[7];
    const float* bc1 = (const float*)d_in[8];
    const float* Wc2 = (const float*)d_in[9];
    const float* bc2 = (const float*)d_in[10];
    const float* W3  = (const float*)d_in[11];
    const float* b3  = (const float*)d_in[12];
    const float* W4  = (const float*)d_in[13];
    const float* b4  = (const float*)d_in[14];
    float* out = (float*)d_out;

    cudaFuncSetAttribute(gemm_v6_kernel, cudaFuncAttributeMaxDynamicSharedMemorySize, GSMEM);
    cudaFuncSetAttribute(gemm12_kernel,  cudaFuncAttributeMaxDynamicSharedMemorySize, GSMEM12);

    void *p;
    float *h, *h0, *hall, *acc, *dinv, *wimg, *bu;
    __half* scal;
    int *cur, *pad;
    cudaGetSymbolAddress(&p, g_h);    h    = (float*)p;
    cudaGetSymbolAddress(&p, g_h0);   h0   = (float*)p;
    cudaGetSymbolAddress(&p, g_hall); hall = (float*)p;
    cudaGetSymbolAddress(&p, g_scal); scal = (__half*)p;
    cudaGetSymbolAddress(&p, g_acc);  acc  = (float*)p;
    cudaGetSymbolAddress(&p, g_dinv); dinv = (float*)p;
    cudaGetSymbolAddress(&p, g_wimg); wimg = (float*)p;
    cudaGetSymbolAddress(&p, g_bu);   bu   = (float*)p;
    cudaGetSymbolAddress(&p, g_cur);  cur  = (int*)p;
    cudaGetSymbolAddress(&p, g_pad);  pad  = (int*)p;

    const int GB = (Nn + 127) / 128;      // 782 gemm blocks
    const int AB = (Nn + 7) / 8;          // 12500 gather blocks

    pack_kernel<<<(Rr * Nn + 255) / 256, 256>>>(W1, W2, Wc1, Wc2, W3, b3, bc2);
    {
        dim3 fg((Ee + 255) / 256, Rr);
        fill_kernel<<<fg, 256>>>(src, dst);
    }
    dinv_kernel<<<(Rr * Nn + 255) / 256, 256>>>();

    // fused: h = act(act(x@W1+b1)@W2+b2); scal = fp16(dinv_r0 * h)
    gemm12_kernel<<<GB, 128, GSMEM12>>>(x, wimg + 0 * WIMG, b1, wimg + 1 * WIMG, b2,
                                        h, dinv, scal);

    for (int r = 0; r < Rr; r++) {
        const float* dv = dinv + (size_t)r * Nn;
        const int*   pr = pad + (size_t)r * Nn * PADSZ;
        const int*   cr = cur + (size_t)r * Nn;

        gather_kernel<<<AB, 256>>>(pr, cr, scal, acc);
        gemm_v6_kernel<<<GB, 128, GSMEM>>>(h, acc, dv, wimg + 2 * WIMG, 2,
                                           bc1, h0, nullptr, 0, 0, dv, scal,
                                           nullptr, nullptr, nullptr);

        gather_kernel<<<AB, 256>>>(pr, cr, scal, acc);
        if (r + 1 < Rr) {
            const float* ndv = dinv + (size_t)(r + 1) * Nn;
            gemm_v6_kernel<<<GB, 128, GSMEM>>>(h0, acc, dv, wimg + 4 * WIMG, 2,
                                               bu, h, hall, (r == 0) ? 1 : 2, 0,
                                               ndv, scal, nullptr, nullptr, nullptr);
        } else {
            gemm_v6_kernel<<<GB, 128, GSMEM>>>(h0, acc, dv, wimg + 4 * WIMG, 2,
                                               bu, h, hall, 3, 0,
                                               nullptr, nullptr, W4, b4, out);
        }
    }
}

// round 17
// speedup vs baseline: 1.4342x; 1.0033x over previous
#include <cuda_runtime.h>
#include <cuda_fp16.h>
#include <cstdint>

#define Nn 100000
#define Ee 1000000
#define Rr 3
#define APAD 132
#define PADSZ 64
#define WROW 72
#define WIMG (64 * WROW)   // 4608 floats per image

// ---------------- scratch (device globals, no allocation) ----------------
__device__ float  g_h   [Nn * 64];
__device__ float  g_h0  [Nn * 64];
__device__ float  g_hall[Nn * 64];
__device__ __half g_scal[Nn * 64];     // fp16 messages (dinv*h)
__device__ float  g_acc [Nn * 64];
__device__ float  g_dinv[Rr * Nn];
__device__ int    g_cur [Rr * Nn];
__device__ int    g_pad [(size_t)Rr * Nn * PADSZ];
__device__ float  g_wimg[6 * WIMG];
__device__ float  g_bu  [64];

// ---------------- helpers ----------------
__device__ __forceinline__ void fma2(unsigned long long& d, unsigned long long a, unsigned long long b) {
    asm("fma.rn.f32x2 %0,%1,%2,%0;" : "+l"(d) : "l"(a), "l"(b));
}
__device__ __forceinline__ unsigned long long pk2s(float a) {
    unsigned long long r;
    asm("mov.b64 %0,{%1,%1};" : "=l"(r) : "f"(a));
    return r;
}
__device__ __forceinline__ float2 upk2(unsigned long long v) {
    float2 f;
    asm("mov.b64 {%0,%1},%2;" : "=f"(f.x), "=f"(f.y) : "l"(v));
    return f;
}
__device__ __forceinline__ float lrelu(float x) { return x > 0.f ? x : 0.01f * x; }
__device__ __forceinline__ unsigned h2u(float a, float b) {
    __half2 h = __floats2half2_rn(a, b);
    return *(unsigned*)&h;
}

// ---------------- pack (+ cursor zero): natural-pair weight images + folded U,V,bU ----------------
// image row k (WROW floats): [half 0: cols 8g..8g+3 by g 0..7][half 1: cols 8g+4..8g+7 by g]
__global__ void pack_kernel(const float* __restrict__ W1, const float* __restrict__ W2,
                            const float* __restrict__ Wc1, const float* __restrict__ Wc2,
                            const float* __restrict__ W3, const float* __restrict__ b3,
                            const float* __restrict__ bc2) {
    int i = blockIdx.x * 256 + threadIdx.x;
    if (i < Rr * Nn) g_cur[i] = 0;
    if (i < 6 * 4096) {
        int img = i >> 12;
        int e   = i & 4095;
        int k = e >> 6, c = e & 63;
        float v;
        if (img == 0)      v = W1[k * 64 + c];
        else if (img == 1) v = W2[k * 64 + c];
        else if (img == 2) v = Wc1[k * 64 + c];
        else if (img == 3) v = Wc1[(64 + k) * 64 + c];
        else if (img == 4) {                       // U = W3t + Wc2t @ W3b
            float s = W3[k * 64 + c];
            for (int j = 0; j < 64; j++) s += Wc2[k * 64 + j] * W3[(64 + j) * 64 + c];
            v = s;
        } else {                                   // V = Wc2b @ W3b
            float s = 0.f;
            for (int j = 0; j < 64; j++) s += Wc2[(64 + k) * 64 + j] * W3[(64 + j) * 64 + c];
            v = s;
        }
        int g = c >> 3, j = c & 7;
        int pos = (j >> 2) * 32 + g * 4 + (j & 3);
        g_wimg[(size_t)img * WIMG + k * WROW + pos] = v;
    } else if (i < 6 * 4096 + 64) {
        int c = i - 6 * 4096;
        float s = b3[c];
        for (int j = 0; j < 64; j++) s += bc2[j] * W3[(64 + j) * 64 + c];
        g_bu[c] = s;
    }
}

// ---------------- adjacency build ----------------
__global__ void fill_kernel(const int* __restrict__ src, const int* __restrict__ dst) {
    int i = blockIdx.x * 256 + threadIdx.x;
    int r = blockIdx.y;
    if (i >= Ee) return;
    int d = dst[(size_t)r * Ee + i];
    int s = src[(size_t)r * Ee + i];
    int slot = atomicAdd(&g_cur[r * Nn + d], 1);
    if (slot < PADSZ) g_pad[((size_t)r * Nn + d) * PADSZ + slot] = s;
}
__global__ void dinv_kernel() {
    int i = blockIdx.x * 256 + threadIdx.x;
    if (i < Rr * Nn) g_dinv[i] = rsqrtf(fmaxf((float)g_cur[i], 1.0f));
}

// ---------------- pull gather (fp16 source): acc[n] = sum scal[src[e]] ----------------
__global__ __launch_bounds__(256) void gather_kernel(
    const int* __restrict__ pad, const int* __restrict__ cur,
    const __half* __restrict__ scal, float* __restrict__ acc)
{
    int n = blockIdx.x * 8 + (threadIdx.x >> 5);
    if (n >= Nn) return;
    int lane2 = (threadIdx.x & 31) * 2;
    int c = cur[n];
    c = c < PADSZ ? c : PADSZ;
    const int* sp = pad + (size_t)n * PADSZ;
    float2 a0 = {0.f, 0.f}, a1 = {0.f, 0.f}, a2 = {0.f, 0.f}, a3 = {0.f, 0.f};
    int i = 0;
    for (; i + 4 <= c; i += 4) {
        int s0 = sp[i], s1 = sp[i + 1], s2 = sp[i + 2], s3 = sp[i + 3];
        float2 v0 = __half22float2(*(const __half2*)(scal + (size_t)s0 * 64 + lane2));
        float2 v1 = __half22float2(*(const __half2*)(scal + (size_t)s1 * 64 + lane2));
        float2 v2 = __half22float2(*(const __half2*)(scal + (size_t)s2 * 64 + lane2));
        float2 v3 = __half22float2(*(const __half2*)(scal + (size_t)s3 * 64 + lane2));
        a0.x += v0.x; a0.y += v0.y;
        a1.x += v1.x; a1.y += v1.y;
        a2.x += v2.x; a2.y += v2.y;
        a3.x += v3.x; a3.y += v3.y;
    }
    for (; i < c; i++) {
        float2 v0 = __half22float2(*(const __half2*)(scal + (size_t)sp[i] * 64 + lane2));
        a0.x += v0.x; a0.y += v0.y;
    }
    a0.x += a1.x + a2.x + a3.x;
    a0.y += a1.y + a2.y + a3.y;
    *(float2*)(acc + (size_t)n * 64 + lane2) = a0;
}

// ======================================================================
// GEMM core (128 threads, tile 128 nodes x 64 cols, thread = 8 nodes x 8 cols)
// ======================================================================
#define GEMM_COMPUTE(As, Wd, n0, g, acc)                                       \
    _Pragma("unroll 8")                                                        \
    for (int k = 0; k < 64; k++) {                                             \
        int pr = ((k & 7) << 3) | (k >> 3);                                    \
        const float* ar = (As) + pr * APAD + (n0);                             \
        float4 af0 = *(const float4*)(ar);                                     \
        float4 af1 = *(const float4*)(ar + 4);                                 \
        const float* wr = (Wd) + k * WROW + (g) * 4;                           \
        ulonglong2 wA = *(const ulonglong2*)(wr);                              \
        ulonglong2 wB = *(const ulonglong2*)(wr + 32);                         \
        unsigned long long an0 = pk2s(af0.x), an1 = pk2s(af0.y);               \
        unsigned long long an2 = pk2s(af0.z), an3 = pk2s(af0.w);               \
        unsigned long long an4 = pk2s(af1.x), an5 = pk2s(af1.y);               \
        unsigned long long an6 = pk2s(af1.z), an7 = pk2s(af1.w);               \
        fma2(acc[0],  an0, wA.x); fma2(acc[1],  an0, wA.y);                    \
        fma2(acc[2],  an0, wB.x); fma2(acc[3],  an0, wB.y);                    \
        fma2(acc[4],  an1, wA.x); fma2(acc[5],  an1, wA.y);                    \
        fma2(acc[6],  an1, wB.x); fma2(acc[7],  an1, wB.y);                    \
        fma2(acc[8],  an2, wA.x); fma2(acc[9],  an2, wA.y);                    \
        fma2(acc[10], an2, wB.x); fma2(acc[11], an2, wB.y);                    \
        fma2(acc[12], an3, wA.x); fma2(acc[13], an3, wA.y);                    \
        fma2(acc[14], an3, wB.x); fma2(acc[15], an3, wB.y);                    \
        fma2(acc[16], an4, wA.x); fma2(acc[17], an4, wA.y);                    \
        fma2(acc[18], an4, wB.x); fma2(acc[19], an4, wB.y);                    \
        fma2(acc[20], an5, wA.x); fma2(acc[21], an5, wA.y);                    \
        fma2(acc[22], an5, wB.x); fma2(acc[23], an5, wB.y);                    \
        fma2(acc[24], an6, wA.x); fma2(acc[25], an6, wA.y);                    \
        fma2(acc[26], an6, wB.x); fma2(acc[27], an6, wB.y);                    \
        fma2(acc[28], an7, wA.x); fma2(acc[29], an7, wA.y);                    \
        fma2(acc[30], an7, wB.x); fma2(acc[31], an7, wB.y);                    \
    }

// unpack node ni's 8 cols (+bias) from acc
#define NODE_V(acc, ni, bi0, bi1, v0, v1)                                      \
    {                                                                          \
        float2 q0 = upk2(acc[(ni) * 4 + 0]);                                   \
        float2 q1 = upk2(acc[(ni) * 4 + 1]);                                   \
        float2 q2 = upk2(acc[(ni) * 4 + 2]);                                   \
        float2 q3 = upk2(acc[(ni) * 4 + 3]);                                   \
        v0 = make_float4(q0.x + bi0.x, q0.y + bi0.y, q1.x + bi0.z, q1.y + bi0.w); \
        v1 = make_float4(q2.x + bi1.x, q2.y + bi1.y, q3.x + bi1.z, q3.y + bi1.w); \
    }

// ---------------- fused GEMM1+GEMM2: h = act(act(x@W1+b1)@W2+b2); prep scal ----------------
__global__ __launch_bounds__(128, 4) void gemm12_kernel(
    const float* __restrict__ x,
    const float* __restrict__ w1img, const float* __restrict__ b1,
    const float* __restrict__ w2img, const float* __restrict__ b2,
    float* __restrict__ C,
    const float* __restrict__ prep_dinv, __half* __restrict__ scal)
{
    extern __shared__ float sm[];
    float* b1s = sm;
    float* b2s = sm + 64;
    float* As  = sm + 128;
    float* Wd  = sm + 128 + 64 * APAD;

    const int tid  = threadIdx.x;
    const int base = blockIdx.x * 128;
    const int g    = tid & 7;
    const int n0   = (tid >> 3) << 3;
    const int c0   = g << 3;

    if (tid < 16)      ((float4*)b1s)[tid]      = ((const float4*)b1)[tid];
    else if (tid < 32) ((float4*)b2s)[tid - 16] = ((const float4*)b2)[tid - 16];

    unsigned long long acc[32];
#pragma unroll
    for (int i = 0; i < 32; i++) acc[i] = 0ull;

    // ---- phase 1: stage W1 (1152 float4 = 9x128) + x ----
    {
        const float4* ws = (const float4*)w1img;
        float4* wdp = (float4*)Wd;
#pragma unroll 3
        for (int j = 0; j < 9; j++) wdp[tid + 128 * j] = ws[tid + 128 * j];
    }
#pragma unroll 4
    for (int it = 0; it < 16; it++) {
        int f  = tid + 128 * it;
        int n  = f >> 4, k4 = f & 15;
        int gnode = base + n;
        float4 v = make_float4(0.f, 0.f, 0.f, 0.f);
        if (gnode < Nn) v = *(const float4*)(x + (size_t)gnode * 64 + k4 * 4);
#pragma unroll
        for (int j = 0; j < 4; j++) {
            int r  = 4 * k4 + j;
            int pr = ((r & 7) << 3) | (r >> 3);
            As[pr * APAD + n] = ((const float*)&v)[j];
        }
    }
    __syncthreads();

    GEMM_COMPUTE(As, Wd, n0, g, acc)
    __syncthreads();

    // ---- write h0 tile (activated) back into As; restage W2 ----
    {
        const float4 bb0 = *(const float4*)(b1s + c0);
        const float4 bb1 = *(const float4*)(b1s + c0 + 4);
#pragma unroll
        for (int ni = 0; ni < 8; ni++) {
            int n = n0 + ni;
            float4 v0, v1;
            NODE_V(acc, ni, bb0, bb1, v0, v1)
            float z[8];
            z[0] = lrelu(v0.x); z[1] = lrelu(v0.y); z[2] = lrelu(v0.z); z[3] = lrelu(v0.w);
            z[4] = lrelu(v1.x); z[5] = lrelu(v1.y); z[6] = lrelu(v1.z); z[7] = lrelu(v1.w);
#pragma unroll
            for (int j = 0; j < 8; j++) {
                int k  = c0 + j;
                int pr = ((k & 7) << 3) | (k >> 3);
                As[pr * APAD + n] = z[j];
            }
        }
        const float4* ws = (const float4*)w2img;
        float4* wdp = (float4*)Wd;
#pragma unroll 3
        for (int j = 0; j < 9; j++) wdp[tid + 128 * j] = ws[tid + 128 * j];
    }
#pragma unroll
    for (int i = 0; i < 32; i++) acc[i] = 0ull;
    __syncthreads();

    GEMM_COMPUTE(As, Wd, n0, g, acc)

    // ---- epilogue: h = act(.+b2); scal = fp16(dinv*h) ----
    const float4 bi0 = *(const float4*)(b2s + c0);
    const float4 bi1 = *(const float4*)(b2s + c0 + 4);
#pragma unroll
    for (int ni = 0; ni < 8; ni++) {
        int gnode = base + n0 + ni;
        if (gnode >= Nn) continue;
        float4 v0, v1;
        NODE_V(acc, ni, bi0, bi1, v0, v1)
        v0.x = lrelu(v0.x); v0.y = lrelu(v0.y); v0.z = lrelu(v0.z); v0.w = lrelu(v0.w);
        v1.x = lrelu(v1.x); v1.y = lrelu(v1.y); v1.z = lrelu(v1.z); v1.w = lrelu(v1.w);
        size_t idx = (size_t)gnode * 64 + c0;
        *(float4*)(C + idx)     = v0;
        *(float4*)(C + idx + 4) = v1;
        float dv = prep_dinv[gnode];
        uint4 hv;
        hv.x = h2u(v0.x * dv, v0.y * dv);
        hv.y = h2u(v0.z * dv, v0.w * dv);
        hv.z = h2u(v1.x * dv, v1.y * dv);
        hv.w = h2u(v1.z * dv, v1.w * dv);
        *(uint4*)(scal + idx) = hv;
    }
}

// ---------------- v6 FFMA2 fused dual GEMM (+ optional fused final head) ----------------
// hall_mode: 0 none, 1 set, 2 add, 3 add-in-reg + out = lrelu(hall+v)@W4+b4
__global__ __launch_bounds__(128, 4) void gemm_v6_kernel(
    const float* __restrict__ A, const float* __restrict__ B,
    const float* __restrict__ rowscaleB,
    const float* __restrict__ wimg, int nchunks,
    const float* __restrict__ bias, float* __restrict__ C,
    float* __restrict__ hall, int hall_mode, int act,
    const float* __restrict__ prep_dinv, __half* __restrict__ scal,
    const float* __restrict__ W4, const float* __restrict__ b4,
    float* __restrict__ out)
{
    extern __shared__ float sm[];
    float* bias_s = sm;
    float* As     = sm + 64;
    float* Wd     = sm + 64 + 64 * APAD;

    const int tid  = threadIdx.x;
    const int base = blockIdx.x * 128;
    const int g    = tid & 7;
    const int n0   = (tid >> 3) << 3;
    const int c0   = g << 3;

    if (tid < 16) ((float4*)bias_s)[tid] = ((const float4*)bias)[tid];

    unsigned long long acc[32];
#pragma unroll
    for (int i = 0; i < 32; i++) acc[i] = 0ull;

    for (int ch = 0; ch < nchunks; ch++) {
        {
            const float4* ws = (const float4*)(wimg + (size_t)ch * WIMG);
            float4* wdp = (float4*)Wd;
#pragma unroll 3
            for (int j = 0; j < 9; j++) wdp[tid + 128 * j] = ws[tid + 128 * j];
        }
        {
            const float* Am = ch ? B : A;
#pragma unroll 4
            for (int it = 0; it < 16; it++) {
                int f  = tid + 128 * it;
                int n  = f >> 4, k4 = f & 15;
                int gnode = base + n;
                float4 v = make_float4(0.f, 0.f, 0.f, 0.f);
                float s = 1.0f;
                if (gnode < Nn) {
                    v = *(const float4*)(Am + (size_t)gnode * 64 + k4 * 4);
                    if (ch == 1 && rowscaleB) s = -rowscaleB[gnode];
                }
                float vv[4] = {v.x * s, v.y * s, v.z * s, v.w * s};
#pragma unroll
                for (int j = 0; j < 4; j++) {
                    int r  = 4 * k4 + j;
                    int pr = ((r & 7) << 3) | (r >> 3);
                    As[pr * APAD + n] = vv[j];
                }
            }
        }
        __syncthreads();

        GEMM_COMPUTE(As, Wd, n0, g, acc)
        __syncthreads();
    }

    const float4 bi0 = *(const float4*)(bias_s + c0);
    const float4 bi1 = *(const float4*)(bias_s + c0 + 4);

    if (hall_mode == 3) {
        // ---- fused final head: out = lrelu(hall + v) @ W4 + b4 ----
        float w4a[8], w4b[8];
#pragma unroll
        for (int j = 0; j < 8; j++) {
            float2 w = *(const float2*)(W4 + (c0 + j) * 2);
            w4a[j] = w.x; w4b[j] = w.y;
        }
        float o0[8], o1[8];
#pragma unroll
        for (int j = 0; j < 8; j++) { o0[j] = 0.f; o1[j] = 0.f; }
#pragma unroll
        for (int ni = 0; ni < 8; ni++) {
            int gnode = base + n0 + ni;
            if (gnode >= Nn) continue;
            size_t idx = (size_t)gnode * 64 + c0;
            float4 h0v = *(const float4*)(hall + idx);
            float4 h1v = *(const float4*)(hall + idx + 4);
            float4 v0, v1;
            NODE_V(acc, ni, bi0, bi1, v0, v1)
            float z0 = lrelu(h0v.x + v0.x);
            float z1 = lrelu(h0v.y + v0.y);
            float z2 = lrelu(h0v.z + v0.z);
            float z3 = lrelu(h0v.w + v0.w);
            float z4 = lrelu(h1v.x + v1.x);
            float z5 = lrelu(h1v.y + v1.y);
            float z6 = lrelu(h1v.z + v1.z);
            float z7 = lrelu(h1v.w + v1.w);
            o0[ni] = z0 * w4a[0] + z1 * w4a[1] + z2 * w4a[2] + z3 * w4a[3]
                   + z4 * w4a[4] + z5 * w4a[5] + z6 * w4a[6] + z7 * w4a[7];
            o1[ni] = z0 * w4b[0] + z1 * w4b[1] + z2 * w4b[2] + z3 * w4b[3]
                   + z4 * w4b[4] + z5 * w4b[5] + z6 * w4b[6] + z7 * w4b[7];
        }
#pragma unroll
        for (int ni = 0; ni < 8; ni++) {
#pragma unroll
            for (int m = 1; m < 8; m <<= 1) {
                o0[ni] += __shfl_xor_sync(0xFFFFFFFFu, o0[ni], m);
                o1[ni] += __shfl_xor_sync(0xFFFFFFFFu, o1[ni], m);
            }
        }
        if (g == 0) {
            float2 bb = *(const float2*)b4;
#pragma unroll
            for (int ni = 0; ni < 8; ni++) {
                int gnode = base + n0 + ni;
                if (gnode < Nn)
                    *(float2*)(out + (size_t)gnode * 2) = make_float2(o0[ni] + bb.x, o1[ni] + bb.y);
            }
        }
        return;
    }

    // ---- standard fused epilogue ----
#pragma unroll
    for (int ni = 0; ni < 8; ni++) {
        int gnode = base + n0 + ni;
        if (gnode >= Nn) continue;
        float4 v0, v1;
        NODE_V(acc, ni, bi0, bi1, v0, v1)
        if (act) {
            v0.x = lrelu(v0.x); v0.y = lrelu(v0.y); v0.z = lrelu(v0.z); v0.w = lrelu(v0.w);
            v1.x = lrelu(v1.x); v1.y = lrelu(v1.y); v1.z = lrelu(v1.z); v1.w = lrelu(v1.w);
        }
        size_t idx = (size_t)gnode * 64 + c0;
        *(float4*)(C + idx)     = v0;
        *(float4*)(C + idx + 4) = v1;
        if (hall_mode == 1) {
            *(float4*)(hall + idx)     = v0;
            *(float4*)(hall + idx + 4) = v1;
        } else if (hall_mode == 2) {
            float4 h0v = *(const float4*)(hall + idx);
            float4 h1v = *(const float4*)(hall + idx + 4);
            h0v.x += v0.x; h0v.y += v0.y; h0v.z += v0.z; h0v.w += v0.w;
            h1v.x += v1.x; h1v.y += v1.y; h1v.z += v1.z; h1v.w += v1.w;
            *(float4*)(hall + idx)     = h0v;
            *(float4*)(hall + idx + 4) = h1v;
        }
        if (scal) {
            float dv = prep_dinv[gnode];
            uint4 hv;
            hv.x = h2u(v0.x * dv, v0.y * dv);
            hv.y = h2u(v0.z * dv, v0.w * dv);
            hv.z = h2u(v1.x * dv, v1.y * dv);
            hv.w = h2u(v1.z * dv, v1.w * dv);
            *(uint4*)(scal + idx) = hv;
        }
    }
}

// ---------------- launch ----------------
#define GSMEM   ((64 + 64 * APAD + 64 * WROW) * 4)    // 52480 bytes
#define GSMEM12 ((128 + 64 * APAD + 64 * WROW) * 4)   // 52736 bytes

extern "C" void kernel_launch(void* const* d_in, const int* in_sizes, int n_in,
                              void* d_out, int out_size)
{
    const float* x   = (const float*)d_in[0];
    const int*   src = (const int*)d_in[1];
    const int*   dst = (const int*)d_in[2];
    const float* W1  = (const float*)d_in[3];
    const float* b1  = (const float*)d_in[4];
    const float* W2  = (const float*)d_in[5];
    const float* b2  = (const float*)d_in[6];
    const float* Wc1 = (const float*)d_in[7];
    const float* bc1 = (const float*)d_in[8];
    const float* Wc2 = (const float*)d_in[9];
    const float* bc2 = (const float*)d_in[10];
    const float* W3  = (const float*)d_in[11];
    const float* b3  = (const float*)d_in[12];
    const float* W4  = (const float*)d_in[13];
    const float* b4  = (const float*)d_in[14];
    float* out = (float*)d_out;

    cudaFuncSetAttribute(gemm_v6_kernel, cudaFuncAttributeMaxDynamicSharedMemorySize, GSMEM);
    cudaFuncSetAttribute(gemm12_kernel,  cudaFuncAttributeMaxDynamicSharedMemorySize, GSMEM12);

    void *p;
    float *h, *h0, *hall, *acc, *dinv, *wimg, *bu;
    __half* scal;
    int *cur, *pad;
    cudaGetSymbolAddress(&p, g_h);    h    = (float*)p;
    cudaGetSymbolAddress(&p, g_h0);   h0   = (float*)p;
    cudaGetSymbolAddress(&p, g_hall); hall = (float*)p;
    cudaGetSymbolAddress(&p, g_scal); scal = (__half*)p;
    cudaGetSymbolAddress(&p, g_acc);  acc  = (float*)p;
    cudaGetSymbolAddress(&p, g_dinv); dinv = (float*)p;
    cudaGetSymbolAddress(&p, g_wimg); wimg = (float*)p;
    cudaGetSymbolAddress(&p, g_bu);   bu   = (float*)p;
    cudaGetSymbolAddress(&p, g_cur);  cur  = (int*)p;
    cudaGetSymbolAddress(&p, g_pad);  pad  = (int*)p;

    const int GB = (Nn + 127) / 128;      // 782 gemm blocks
    const int AB = (Nn + 7) / 8;          // 12500 gather blocks

    pack_kernel<<<(Rr * Nn + 255) / 256, 256>>>(W1, W2, Wc1, Wc2, W3, b3, bc2);
    {
        dim3 fg((Ee + 255) / 256, Rr);
        fill_kernel<<<fg, 256>>>(src, dst);
    }
    dinv_kernel<<<(Rr * Nn + 255) / 256, 256>>>();

    // fused: h = act(act(x@W1+b1)@W2+b2); scal = fp16(dinv_r0 * h)
    gemm12_kernel<<<GB, 128, GSMEM12>>>(x, wimg + 0 * WIMG, b1, wimg + 1 * WIMG, b2,
                                        h, dinv, scal);

    for (int r = 0; r < Rr; r++) {
        const float* dv = dinv + (size_t)r * Nn;
        const int*   pr = pad + (size_t)r * Nn * PADSZ;
        const int*   cr = cur + (size_t)r * Nn;

        gather_kernel<<<AB, 256>>>(pr, cr, scal, acc);
        gemm_v6_kernel<<<GB, 128, GSMEM>>>(h, acc, dv, wimg + 2 * WIMG, 2,
                                           bc1, h0, nullptr, 0, 0, dv, scal,
                                           nullptr, nullptr, nullptr);

        gather_kernel<<<AB, 256>>>(pr, cr, scal, acc);
        if (r + 1 < Rr) {
            const float* ndv = dinv + (size_t)(r + 1) * Nn;
            gemm_v6_kernel<<<GB, 128, GSMEM>>>(h0, acc, dv, wimg + 4 * WIMG, 2,
                                               bu, h, hall, (r == 0) ? 1 : 2, 0,
                                               ndv, scal, nullptr, nullptr, nullptr);
        } else {
            gemm_v6_kernel<<<GB, 128, GSMEM>>>(h0, acc, dv, wimg + 4 * WIMG, 2,
                                               bu, h, hall, 3, 0,
                                               nullptr, nullptr, W4, b4, out);
        }
    }
}